// round 8
// baseline (speedup 1.0000x reference)
#include <cuda_runtime.h>
#include <math.h>

// Problem constants
#define BATCH 32768
#define UDIM  256

// ---------------------------------------------------------------------------
// Static device scratch (no allocation allowed)
// ---------------------------------------------------------------------------
__device__ float g_rhs[BATCH * 512];       // [B, 512]: cols 0..255 = r_u, 256..511 = r_v (64 MB)
__device__ float g_du [BATCH * 256];       // [B, 256]: u of current layer (negated un)      (32 MB)
__device__ float g_WiT[256 * 256];         // Wi transposed -> NN gemm
__device__ float g_E  [4 * 65536];         // E = 0.01 W W^T per layer
__device__ float g_T  [4 * 65536];         // Neumann temp
__device__ float g_T2 [4 * 65536];         // Neumann temp
__device__ float g_C  [4 * 512 * 256];     // per-layer [512,256]: top = Minv, bottom = -0.1 W^T Minv

struct W4p { const float* w[4]; };

// ---------------------------------------------------------------------------
// Prep kernels (tiny 256x256 GEMMs, batched over layers via blockIdx.z)
// ---------------------------------------------------------------------------
__global__ void k_transpose(const float* __restrict__ Wi) {
    int idx = blockIdx.x * 256 + threadIdx.x;   // idx = k*256 + j
    int k = idx >> 8, j = idx & 255;
    g_WiT[idx] = Wi[j * 256 + k];
}

// E = 0.01 * W W^T ; T = I - E
__global__ void k_syrk(W4p ws) {
    int z = blockIdx.z;
    const float* __restrict__ W = ws.w[z];
    __shared__ float As[16][17], Bs[16][17];
    int tx = threadIdx.x, ty = threadIdx.y;
    int i = blockIdx.y * 16 + ty;
    int j = blockIdx.x * 16 + tx;
    float acc = 0.f;
    for (int kt = 0; kt < 256; kt += 16) {
        As[ty][tx] = W[i * 256 + kt + tx];
        Bs[ty][tx] = W[(blockIdx.x * 16 + ty) * 256 + kt + tx];
        __syncthreads();
#pragma unroll
        for (int k = 0; k < 16; ++k) acc += As[ty][k] * Bs[tx][k];
        __syncthreads();
    }
    float e = 0.01f * acc;
    int idx = z * 65536 + i * 256 + j;
    g_E[idx] = e;
    g_T[idx] = (i == j ? 1.f : 0.f) - e;
}

// PHASE 0: T2 = I - E*T ; PHASE 1: C_top = I - E*T2  (= Minv, Neumann to E^3)
template<int PHASE>
__global__ void k_step() {
    int z = blockIdx.z;
    const float* __restrict__ E   = g_E + z * 65536;
    const float* __restrict__ Tin = (PHASE ? g_T2 : g_T) + z * 65536;
    __shared__ float As[16][17], Bs[16][17];
    int tx = threadIdx.x, ty = threadIdx.y;
    int i = blockIdx.y * 16 + ty;
    int j = blockIdx.x * 16 + tx;
    float acc = 0.f;
    for (int kt = 0; kt < 256; kt += 16) {
        As[ty][tx] = E[i * 256 + kt + tx];
        Bs[ty][tx] = Tin[(kt + ty) * 256 + blockIdx.x * 16 + tx];
        __syncthreads();
#pragma unroll
        for (int k = 0; k < 16; ++k) acc += As[ty][k] * Bs[k][tx];
        __syncthreads();
    }
    float r = (i == j ? 1.f : 0.f) - acc;
    if (PHASE == 0) g_T2[z * 65536 + i * 256 + j] = r;
    else            g_C [z * 131072 + i * 256 + j] = r;
}

// C_bottom = -0.1 * W^T * Minv   (Minv = C_top)
__global__ void k_tn(W4p ws) {
    int z = blockIdx.z;
    const float* __restrict__ W    = ws.w[z];
    const float* __restrict__ Minv = g_C + z * 131072;
    __shared__ float As[16][17], Bs[16][17];
    int tx = threadIdx.x, ty = threadIdx.y;
    int i = blockIdx.y * 16 + ty;
    int j = blockIdx.x * 16 + tx;
    float acc = 0.f;
    for (int kt = 0; kt < 256; kt += 16) {
        As[ty][tx] = W   [(kt + ty) * 256 + blockIdx.y * 16 + tx];
        Bs[ty][tx] = Minv[(kt + ty) * 256 + blockIdx.x * 16 + tx];
        __syncthreads();
#pragma unroll
        for (int k = 0; k < 16; ++k) acc += As[k][ty] * Bs[k][tx];
        __syncthreads();
    }
    g_C[z * 131072 + (256 + i) * 256 + j] = -0.1f * acc;
}

// ---------------------------------------------------------------------------
// Main batched GEMM: C[B x 256] = A[B x K] * Bm[K x 256] with fused epilogue
// MODE 0 (input):  A = x, Bm = WiT.  z = acc + bi[col];
//                  rhs[:, col]     = z + 0.1*b1[col]       (r_u)
//                  rhs[:, 256+col] = tanh(z)               (r_v, exact here)
// MODE 1 (solve):  A = g_rhs (K=512), Bm = g_C[layer].  du = -acc  (= u_out)
// MODE 2 (mix):    A = g_du, Bm = W_l.  acc = du*W.
//                  u = du;  rv_old = rhs[:,256+col]
//                  rhs[:, col]     = u + 0.1*b_next[col]
//                  rhs[:, 256+col] = (10*tanh(u) - 0.9*acc - rv_old) / 11
// ---------------------------------------------------------------------------
template<int MODE, int K, int LDA>
__global__ __launch_bounds__(256, 2)
void sgemm(const float* __restrict__ P0,
           const float* __restrict__ b1,
           const float* __restrict__ b2,
           int layer)
{
    const float* A  = (MODE == 0) ? P0 : (MODE == 1 ? g_rhs : g_du);
    const float* Bm = (MODE == 0) ? g_WiT : (MODE == 1 ? (g_C + layer * 131072) : P0);

    __shared__ float As[2][8][128];
    __shared__ float Bs[2][8][128];

    const int tid = threadIdx.x;
    const int bm = blockIdx.x, bn = blockIdx.y;
    const int tx = tid & 15, ty = tid >> 4;
    const int arow = tid >> 1, acol = (tid & 1) * 4;
    const int brow = tid >> 5, bcol = (tid & 31) * 4;

    const float* Ap = A + (bm * 128 + arow) * LDA + acol;
    const float* Bp = Bm + brow * 256 + bn * 128 + bcol;

    float acc[8][8];
#pragma unroll
    for (int i = 0; i < 8; ++i)
#pragma unroll
        for (int j = 0; j < 8; ++j) acc[i][j] = 0.f;

    float4 av = *(const float4*)Ap;
    float4 bv = *(const float4*)Bp;
    As[0][acol + 0][arow] = av.x; As[0][acol + 1][arow] = av.y;
    As[0][acol + 2][arow] = av.z; As[0][acol + 3][arow] = av.w;
    *(float4*)&Bs[0][brow][bcol] = bv;
    __syncthreads();

    const int KT = K / 8;
    for (int kt = 0; kt < KT; ++kt) {
        const int cur = kt & 1;
        if (kt + 1 < KT) {
            av = *(const float4*)(Ap + (kt + 1) * 8);
            bv = *(const float4*)(Bp + (kt + 1) * 8 * 256);
        }
#pragma unroll
        for (int kk = 0; kk < 8; ++kk) {
            float4 a0 = *(const float4*)&As[cur][kk][ty * 8];
            float4 a1 = *(const float4*)&As[cur][kk][ty * 8 + 4];
            float4 b0 = *(const float4*)&Bs[cur][kk][tx * 8];
            float4 b1v = *(const float4*)&Bs[cur][kk][tx * 8 + 4];
            float a[8] = {a0.x, a0.y, a0.z, a0.w, a1.x, a1.y, a1.z, a1.w};
            float b[8] = {b0.x, b0.y, b0.z, b0.w, b1v.x, b1v.y, b1v.z, b1v.w};
#pragma unroll
            for (int i = 0; i < 8; ++i)
#pragma unroll
                for (int j = 0; j < 8; ++j)
                    acc[i][j] += a[i] * b[j];
        }
        if (kt + 1 < KT) {
            const int nxt = cur ^ 1;
            As[nxt][acol + 0][arow] = av.x; As[nxt][acol + 1][arow] = av.y;
            As[nxt][acol + 2][arow] = av.z; As[nxt][acol + 3][arow] = av.w;
            *(float4*)&Bs[nxt][brow][bcol] = bv;
            __syncthreads();
        }
    }

    const int row0 = bm * 128 + ty * 8;
    const int col0 = bn * 128 + tx * 8;

    if (MODE == 1) {
#pragma unroll
        for (int i = 0; i < 8; ++i) {
            int base = (row0 + i) * 256 + col0;
            float4 v0 = make_float4(-acc[i][0], -acc[i][1], -acc[i][2], -acc[i][3]);
            float4 v1 = make_float4(-acc[i][4], -acc[i][5], -acc[i][6], -acc[i][7]);
            *(float4*)&g_du[base]     = v0;
            *(float4*)&g_du[base + 4] = v1;
        }
    } else if (MODE == 0) {
        float bb[8], cc[8];
#pragma unroll
        for (int j = 0; j < 8; ++j) { bb[j] = b1[col0 + j]; cc[j] = b2[col0 + j]; }
#pragma unroll
        for (int i = 0; i < 8; ++i) {
            int rbase = (row0 + i) * 512 + col0;
            float ru[8], rv[8];
#pragma unroll
            for (int j = 0; j < 8; ++j) {
                float z = acc[i][j] + bb[j];
                ru[j] = z + 0.1f * cc[j];
                rv[j] = tanhf(z);
            }
            *(float4*)&g_rhs[rbase]           = make_float4(ru[0], ru[1], ru[2], ru[3]);
            *(float4*)&g_rhs[rbase + 4]       = make_float4(ru[4], ru[5], ru[6], ru[7]);
            *(float4*)&g_rhs[rbase + 256]     = make_float4(rv[0], rv[1], rv[2], rv[3]);
            *(float4*)&g_rhs[rbase + 256 + 4] = make_float4(rv[4], rv[5], rv[6], rv[7]);
        }
    } else { // MODE == 2
        float bb[8];
#pragma unroll
        for (int j = 0; j < 8; ++j) bb[j] = b1[col0 + j];
#pragma unroll
        for (int i = 0; i < 8; ++i) {
            int du_base = (row0 + i) * 256 + col0;
            int r_base  = (row0 + i) * 512 + col0;
            float4 u0 = *(const float4*)&g_du[du_base];
            float4 u1 = *(const float4*)&g_du[du_base + 4];
            float4 rv0 = *(const float4*)&g_rhs[r_base + 256];
            float4 rv1 = *(const float4*)&g_rhs[r_base + 256 + 4];
            float u[8]  = {u0.x, u0.y, u0.z, u0.w, u1.x, u1.y, u1.z, u1.w};
            float rv[8] = {rv0.x, rv0.y, rv0.z, rv0.w, rv1.x, rv1.y, rv1.z, rv1.w};
            float nru[8], nrv[8];
#pragma unroll
            for (int j = 0; j < 8; ++j) {
                nru[j] = u[j] + 0.1f * bb[j];
                nrv[j] = (10.f * tanhf(u[j]) - 0.9f * acc[i][j] - rv[j]) * (1.0f / 11.0f);
            }
            *(float4*)&g_rhs[r_base]           = make_float4(nru[0], nru[1], nru[2], nru[3]);
            *(float4*)&g_rhs[r_base + 4]       = make_float4(nru[4], nru[5], nru[6], nru[7]);
            *(float4*)&g_rhs[r_base + 256]     = make_float4(nrv[0], nrv[1], nrv[2], nrv[3]);
            *(float4*)&g_rhs[r_base + 256 + 4] = make_float4(nrv[4], nrv[5], nrv[6], nrv[7]);
        }
    }
}

// ---------------------------------------------------------------------------
// Output: logits = du @ Wo^T + bo ; softmax over 10 classes.
// One warp per batch row; Wo cached in shared.
// ---------------------------------------------------------------------------
__global__ void out_kernel(const float* __restrict__ Wo,
                           const float* __restrict__ bo,
                           float* __restrict__ out)
{
    __shared__ float sWo[10 * 256];
    __shared__ float sbo[10];
    for (int i = threadIdx.x; i < 2560; i += 128) sWo[i] = Wo[i];
    if (threadIdx.x < 10) sbo[threadIdx.x] = bo[threadIdx.x];
    __syncthreads();

    const int warp = threadIdx.x >> 5;
    const int lane = threadIdx.x & 31;
    const int row = blockIdx.x * 4 + warp;
    const float* u = g_du + row * 256;

    float p[10];
#pragma unroll
    for (int o = 0; o < 10; ++o) p[o] = 0.f;

#pragma unroll
    for (int i = 0; i < 8; ++i) {
        int k = lane + 32 * i;
        float x = u[k];
#pragma unroll
        for (int o = 0; o < 10; ++o) p[o] += x * sWo[o * 256 + k];
    }
#pragma unroll
    for (int off = 16; off > 0; off >>= 1) {
#pragma unroll
        for (int o = 0; o < 10; ++o)
            p[o] += __shfl_xor_sync(0xffffffffu, p[o], off);
    }

    float l[10];
#pragma unroll
    for (int o = 0; o < 10; ++o) l[o] = p[o] + sbo[o];
    float m = l[0];
#pragma unroll
    for (int o = 1; o < 10; ++o) m = fmaxf(m, l[o]);
    float e[10], s = 0.f;
#pragma unroll
    for (int o = 0; o < 10; ++o) { e[o] = expf(l[o] - m); s += e[o]; }
    float inv = 1.f / s;
#pragma unroll
    for (int o = 0; o < 10; ++o)
        if (lane == o) out[row * 10 + o] = e[o] * inv;
}

// ---------------------------------------------------------------------------
// Launch
// ---------------------------------------------------------------------------
extern "C" void kernel_launch(void* const* d_in, const int* in_sizes, int n_in,
                              void* d_out, int out_size)
{
    (void)in_sizes; (void)n_in; (void)out_size;
    const float* x  = (const float*)d_in[0];
    const float* Wi = (const float*)d_in[1];
    const float* bi = (const float*)d_in[2];
    const float* W1 = (const float*)d_in[3];
    const float* b1 = (const float*)d_in[4];
    const float* W2 = (const float*)d_in[5];
    const float* b2 = (const float*)d_in[6];
    const float* W3 = (const float*)d_in[7];
    const float* b3 = (const float*)d_in[8];
    const float* W4 = (const float*)d_in[9];
    const float* b4 = (const float*)d_in[10];
    const float* Wo = (const float*)d_in[11];
    const float* bo = (const float*)d_in[12];
    float* out = (float*)d_out;

    // --- prep: WiT, per-layer C = [Minv ; -0.1 W^T Minv] via Neumann series ---
    k_transpose<<<256, 256>>>(Wi);
    W4p ws; ws.w[0] = W1; ws.w[1] = W2; ws.w[2] = W3; ws.w[3] = W4;
    dim3 gs(16, 16, 4), bs(16, 16);
    k_syrk<<<gs, bs>>>(ws);
    k_step<0><<<gs, bs>>>();
    k_step<1><<<gs, bs>>>();
    k_tn<<<gs, bs>>>(ws);

    // --- main pipeline ---
    dim3 gg(BATCH / 128, 2);
    // input: z = x Wi^T + bi -> rhs for layer 1
    sgemm<0, 256, 256><<<gg, 256>>>(x, bi, b1, 0);
    // layer 1
    sgemm<1, 512, 512><<<gg, 256>>>(nullptr, nullptr, nullptr, 0);
    sgemm<2, 256, 256><<<gg, 256>>>(W1, b2, nullptr, 0);
    // layer 2
    sgemm<1, 512, 512><<<gg, 256>>>(nullptr, nullptr, nullptr, 1);
    sgemm<2, 256, 256><<<gg, 256>>>(W2, b3, nullptr, 0);
    // layer 3
    sgemm<1, 512, 512><<<gg, 256>>>(nullptr, nullptr, nullptr, 2);
    sgemm<2, 256, 256><<<gg, 256>>>(W3, b4, nullptr, 0);
    // layer 4 (only u needed)
    sgemm<1, 512, 512><<<gg, 256>>>(nullptr, nullptr, nullptr, 3);

    // output head + softmax
    out_kernel<<<BATCH / 4, 128>>>(Wo, bo, out);
}